// round 12
// baseline (speedup 1.0000x reference)
#include <cuda_runtime.h>
#include <cuda_bf16.h>
#include <cstdint>

// Static scratch (no allocations allowed). Sized for V <= 4M, n_he <= 8M.
// Fixed-capacity bucket table: 16 slots per vertex -> 64 MB at V = 1M,
// which stays L2-resident during the fill pass (R8's 128 MB table did not —
// that was the measured failure mode). Degrees ~ Poisson(6):
// P(deg > 16) ~ 1.6e-4, so ~160 vertices spill to the exact overflow path.
#define SLOT_CAP   16
#define SLOT_SHIFT 4
#define OVER_MAX   (8 << 20)

__device__ int g_counts[4u << 20];                 // true per-vertex valence
__device__ int g_slots[(4u << 20) * SLOT_CAP];     // first 16 edge ids / vertex
__device__ int g_over_cnt;                         // overflow list length
__device__ int g_over[OVER_MAX];                   // overflow edge ids

// ---------------------------------------------------------------------------
// Pass 1: single-pass inverse-map build. One returning atomic + one scattered
// store per edge (same op count as a perm pass) — but NO histogram and NO
// prefix scan. Edges beyond slot 16 go to the exact-fixup overflow list.
// ---------------------------------------------------------------------------
__global__ void fill_kernel(const int* __restrict__ ids, int n)
{
    int i = blockIdx.x * blockDim.x + threadIdx.x;
    if (i < n) {
        int v = __ldg(ids + i);
        int pos = atomicAdd(&g_counts[v], 1);
        if (pos < SLOT_CAP) {
            g_slots[(v << SLOT_SHIFT) + pos] = i;
        } else {
            int o = atomicAdd(&g_over_cnt, 1);
            if (o < OVER_MAX) g_over[o] = i;
        }
    }
}

// ---------------------------------------------------------------------------
// Pass 2: gather + mean (measured-best R7 inner structure). 8 threads per
// vertex; thread s covers feature quad s as one float4 (group = one 128B
// edge row per load). Per 8-edge chunk every thread loads all 8 slot entries
// (1 fetch + 7 L1-broadcast hits) -> load->load address chain, high MLP.
// Sums the first min(deg,16) edges but divides by the TRUE degree; the
// overflow fixup adds the missing contributions afterward.
// ---------------------------------------------------------------------------
__global__ void gather_kernel(const float4* __restrict__ x4,
                              float4* __restrict__ out4, int V)
{
    long long t = (long long)blockIdx.x * blockDim.x + threadIdx.x;
    int v = (int)(t >> 3);          // vertex
    int s = (int)(t & 7);           // quad index within the 32-dim row
    if (v >= V) return;

    int deg = __ldg(&g_counts[v]);
    int cap = (deg < SLOT_CAP) ? deg : SLOT_CAP;
    const int* slots = g_slots + ((long long)v << SLOT_SHIFT);

    float4 acc = make_float4(0.f, 0.f, 0.f, 0.f);

    for (int base = 0; base < cap; base += 8) {
        int e[8];
        #pragma unroll
        for (int u = 0; u < 8; u++) {
            int j = base + u;
            e[u] = (j < cap) ? __ldg(slots + j) : -1;
        }
        #pragma unroll
        for (int u = 0; u < 8; u++) {
            if (e[u] >= 0) {
                float4 a = __ldg(x4 + (long long)e[u] * 8 + s);
                acc.x += a.x; acc.y += a.y; acc.z += a.z; acc.w += a.w;
            }
        }
    }

    float inv = 1.0f / fmaxf((float)deg, 1.0f);
    out4[(long long)v * 8 + s] =
        make_float4(acc.x * inv, acc.y * inv, acc.z * inv, acc.w * inv);
}

// ---------------------------------------------------------------------------
// Pass 3: exact fixup for overflow edges (expected ~hundreds). Each entry
// REDs x[e]/deg into the already-written mean row of its vertex.
// ---------------------------------------------------------------------------
__global__ void fixup_kernel(const float4* __restrict__ x4,
                             const int* __restrict__ ids,
                             float* __restrict__ out)
{
    int cnt = g_over_cnt;
    if (cnt > OVER_MAX) cnt = OVER_MAX;
    int stride = gridDim.x * blockDim.x;
    for (int i = blockIdx.x * blockDim.x + threadIdx.x; i < cnt; i += stride) {
        int e = g_over[i];
        int v = __ldg(ids + e);
        float inv = 1.0f / (float)__ldg(&g_counts[v]);   // deg > 16 here
        float* dst = out + (long long)v * 32;
        #pragma unroll
        for (int s = 0; s < 8; s++) {
            float4 a = __ldg(x4 + (long long)e * 8 + s);
            asm volatile("red.global.add.v4.f32 [%0], {%1, %2, %3, %4};"
                         :: "l"(dst + s * 4),
                            "f"(a.x * inv), "f"(a.y * inv),
                            "f"(a.z * inv), "f"(a.w * inv)
                         : "memory");
        }
    }
}

extern "C" void kernel_launch(void* const* d_in, const int* in_sizes, int n_in,
                              void* d_out, int out_size)
{
    const float4* x4  = (const float4*)d_in[0];
    const int*    ids = (const int*)d_in[1];

    int n_he = in_sizes[1];                     // element count of vertex_ids
    int V    = (int)((long long)out_size / 32); // output is [V, 32]

    // Zero the valence counters and the overflow counter
    // (slots need no clearing — counts gate all reads).
    void* p = nullptr;
    cudaGetSymbolAddress(&p, g_counts);
    cudaMemsetAsync(p, 0, (size_t)V * sizeof(int));
    cudaGetSymbolAddress(&p, g_over_cnt);
    cudaMemsetAsync(p, 0, sizeof(int));

    // Pass 1: bucket fill (the only O(n_he) atomic pass; no hist, no scan).
    fill_kernel<<<(n_he + 255) / 256, 256>>>(ids, n_he);

    // Pass 2: gather + mean, 8 threads per vertex.
    {
        long long total = (long long)V * 8;
        int threads = 256;
        int blocks = (int)((total + threads - 1) / threads);
        gather_kernel<<<blocks, threads>>>(x4, (float4*)d_out, V);
    }

    // Pass 3: exact overflow fixup (tiny).
    fixup_kernel<<<64, 256>>>(x4, ids, (float*)d_out);
}

// round 13
// speedup vs baseline: 1.0589x; 1.0589x over previous
#include <cuda_runtime.h>
#include <cuda_bf16.h>
#include <cstdint>

// Static scratch (no allocations allowed). Sized for V <= 4M, n_he <= 8M.
__device__ int g_counts[4u << 20];      // histogram
__device__ int g_offsets[4u << 20];     // block-local excl offsets -> incl ends
__device__ int g_blocksums[1024];       // global excl offsets of 4096-v blocks
__device__ int g_perm[8u << 20];        // edge indices grouped by vertex

// ---------------------------------------------------------------------------
// Warp-shuffle inclusive scan helper.
// ---------------------------------------------------------------------------
__device__ __forceinline__ int warp_incl_scan(int v)
{
    #pragma unroll
    for (int d = 1; d < 32; d <<= 1) {
        int t = __shfl_up_sync(0xffffffffu, v, d);
        if ((threadIdx.x & 31) >= d) v += t;
    }
    return v;
}

// ---------------------------------------------------------------------------
// Pass A: histogram of vertex ids (int4-vectorized id stream).
// ---------------------------------------------------------------------------
__global__ void hist_kernel(const int4* __restrict__ ids4, int nq,
                            const int* __restrict__ ids, int n)
{
    int i = blockIdx.x * blockDim.x + threadIdx.x;
    if (i < nq) {
        int4 v = __ldg(ids4 + i);
        atomicAdd(&g_counts[v.x], 1);
        atomicAdd(&g_counts[v.y], 1);
        atomicAdd(&g_counts[v.z], 1);
        atomicAdd(&g_counts[v.w], 1);
    }
    if (i == 0) {
        for (int j = nq * 4; j < n; j++) atomicAdd(&g_counts[__ldg(ids + j)], 1);
    }
}

// ---------------------------------------------------------------------------
// Scan step 1: per-block exclusive scan over 4096 counts (int4 per thread).
// ---------------------------------------------------------------------------
__global__ void scan1_kernel(int V)
{
    __shared__ int wsum[32];
    int i0 = blockIdx.x * 4096 + threadIdx.x * 4;

    int4 c = make_int4(0, 0, 0, 0);
    if (i0 + 3 < V) {
        c = *(const int4*)(g_counts + i0);
    } else {
        if (i0 + 0 < V) c.x = g_counts[i0 + 0];
        if (i0 + 1 < V) c.y = g_counts[i0 + 1];
        if (i0 + 2 < V) c.z = g_counts[i0 + 2];
        if (i0 + 3 < V) c.w = g_counts[i0 + 3];
    }
    int ts = c.x + c.y + c.z + c.w;

    int incl = warp_incl_scan(ts);
    int lane = threadIdx.x & 31, wid = threadIdx.x >> 5;
    if (lane == 31) wsum[wid] = incl;
    __syncthreads();
    if (wid == 0) {
        int w = wsum[lane];
        int ws = warp_incl_scan(w);
        wsum[lane] = ws - w;
    }
    __syncthreads();
    int excl = incl - ts + wsum[wid];

    int4 o;
    o.x = excl;
    o.y = o.x + c.x;
    o.z = o.y + c.y;
    o.w = o.z + c.z;
    if (i0 + 3 < V) {
        *(int4*)(g_offsets + i0) = o;
    } else {
        if (i0 + 0 < V) g_offsets[i0 + 0] = o.x;
        if (i0 + 1 < V) g_offsets[i0 + 1] = o.y;
        if (i0 + 2 < V) g_offsets[i0 + 2] = o.z;
        if (i0 + 3 < V) g_offsets[i0 + 3] = o.w;
    }
    if (threadIdx.x == 1023) g_blocksums[blockIdx.x] = excl + ts;
}

// ---------------------------------------------------------------------------
// Scan step 2: single-block exclusive scan of block sums.
// ---------------------------------------------------------------------------
__global__ void scan2_kernel(int nb)
{
    __shared__ int wsum[32];
    __shared__ int carry_s;
    if (threadIdx.x == 0) carry_s = 0;
    __syncthreads();
    for (int base = 0; base < nb; base += 1024) {
        int i = base + threadIdx.x;
        int v = (i < nb) ? g_blocksums[i] : 0;
        int incl = warp_incl_scan(v);
        int lane = threadIdx.x & 31, wid = threadIdx.x >> 5;
        if (lane == 31) wsum[wid] = incl;
        __syncthreads();
        if (wid == 0) {
            int w = wsum[lane];
            int ws = warp_incl_scan(w);
            wsum[lane] = ws - w;
        }
        __syncthreads();
        int excl = incl - v + wsum[wid] + carry_s;
        if (i < nb) g_blocksums[i] = excl;
        __syncthreads();
        if (threadIdx.x == 1023) carry_s = excl + v;
        __syncthreads();
    }
}

// ---------------------------------------------------------------------------
// Pass B: counting-sort of edge INDICES by vertex id (scalar returning atomic
// per edge — measured L2-atomic floor). Global pos = block-local cursor bump
// + global 4096-block offset (<=1KB, L1-resident).
// Post: g_offsets[v] == block-local inclusive end of segment v.
// ---------------------------------------------------------------------------
__global__ void perm_kernel(const int* __restrict__ ids, int n)
{
    int i = blockIdx.x * blockDim.x + threadIdx.x;
    if (i < n) {
        int v = __ldg(ids + i);
        int pos = atomicAdd(&g_offsets[v], 1) + __ldg(&g_blocksums[v >> 12]);
        g_perm[pos] = i;
    }
}

// ---------------------------------------------------------------------------
// Pass C: gather + mean (measured-best inner structure), launched with
// 128-thread blocks: 4-warp CTAs repack far better under per-vertex degree
// variance (15 CTAs/SM theoretical vs 7), raising achieved occupancy and
// outstanding-load count for the random 128B row reads.
// 8 threads per vertex; thread s covers feature quad s as one float4.
// ---------------------------------------------------------------------------
__global__ void __launch_bounds__(128)
gather_kernel(const float4* __restrict__ x4, float4* __restrict__ out4, int V)
{
    long long t = (long long)blockIdx.x * blockDim.x + threadIdx.x;
    int v = (int)(t >> 3);          // vertex
    int s = (int)(t & 7);           // quad index within the 32-dim row
    if (v >= V) return;

    int beg = (v == 0) ? 0
            : __ldg(&g_offsets[v - 1]) + __ldg(&g_blocksums[(v - 1) >> 12]);
    int end = __ldg(&g_offsets[v]) + __ldg(&g_blocksums[v >> 12]);
    int deg = end - beg;

    float4 acc = make_float4(0.f, 0.f, 0.f, 0.f);

    for (int base = beg; base < end; base += 8) {
        int e[8];
        #pragma unroll
        for (int u = 0; u < 8; u++) {
            int j = base + u;
            e[u] = (j < end) ? __ldg(&g_perm[j]) : -1;
        }
        #pragma unroll
        for (int u = 0; u < 8; u++) {
            if (e[u] >= 0) {
                float4 a = __ldg(x4 + (long long)e[u] * 8 + s);
                acc.x += a.x; acc.y += a.y; acc.z += a.z; acc.w += a.w;
            }
        }
    }

    float inv = 1.0f / fmaxf((float)deg, 1.0f);
    out4[(long long)v * 8 + s] =
        make_float4(acc.x * inv, acc.y * inv, acc.z * inv, acc.w * inv);
}

extern "C" void kernel_launch(void* const* d_in, const int* in_sizes, int n_in,
                              void* d_out, int out_size)
{
    const float4* x4  = (const float4*)d_in[0];
    const int*    ids = (const int*)d_in[1];

    int n_he = in_sizes[1];                     // element count of vertex_ids
    int V    = (int)((long long)out_size / 32); // output is [V, 32]
    int nq   = n_he >> 2;                       // int4 quads in the id stream

    // Zero the histogram.
    void* counts_ptr = nullptr;
    cudaGetSymbolAddress(&counts_ptr, g_counts);
    cudaMemsetAsync(counts_ptr, 0, (size_t)V * sizeof(int));

    // Pass A: histogram (vectorized id stream).
    hist_kernel<<<(nq + 255) / 256, 256>>>((const int4*)ids, nq, ids, n_he);

    // Exclusive scan: 4096-wide blocks, single-iteration top scan.
    int nb = (V + 4095) / 4096;
    scan1_kernel<<<nb, 1024>>>(V);
    scan2_kernel<<<1, 1024>>>(nb);

    // Pass B: permutation (scalar atomics, blocksums folded in).
    perm_kernel<<<(n_he + 255) / 256, 256>>>(ids, n_he);

    // Pass C: gather + mean, 8 threads per vertex, 128-thread blocks.
    {
        long long total = (long long)V * 8;
        int threads = 128;
        int blocks = (int)((total + threads - 1) / threads);
        gather_kernel<<<blocks, threads>>>(x4, (float4*)d_out, V);
    }
}

// round 14
// speedup vs baseline: 1.1723x; 1.1071x over previous
#include <cuda_runtime.h>
#include <cuda_bf16.h>
#include <cstdint>

// ---------------------------------------------------------------------------
// Two-level counting sort + gather.
//   P1: coarse-bin edges into 4096-vertex buckets (smem staging, coalesced
//       global writes, ~1 global atomic per bucket per block).
//   P2: per-bucket fine sort entirely in smem -> dense g_perm + offsets.
//   P3: gather + mean (measured-best inner loop).
//   P4: exact fixup for bucket-capacity overflow (normally empty).
// ---------------------------------------------------------------------------
#define VB_SHIFT   12
#define VB         4096                 // vertices per coarse bucket
#define NBUCK_MAX  512                  // supports V <= 2M
#define CAP_B      32768                // binned-edge capacity per bucket
#define EPB        4096                 // edges per P1 block
#define P1_THREADS 512
#define OVER_MAX   (1 << 20)

__device__ int2 g_bucket[(size_t)NBUCK_MAX * CAP_B];  // coarse bins (e, v)
__device__ int  g_bucket_cnt[NBUCK_MAX];              // edges per bucket
__device__ int  g_offsets[2u << 20];                  // global inclusive ends
__device__ int  g_perm[8u << 20];                     // dense sorted edge ids
__device__ int  g_ovcnt[2u << 20];                    // per-vertex overflow
__device__ int  g_over_n;
__device__ int2 g_over[OVER_MAX];                     // overflow (e, v)

// ---------------------------------------------------------------------------
// P1: coarse binning. Per 4096-edge block: smem histogram over buckets,
// smem scan, one global atomic reservation per touched bucket, smem staging,
// coalesced flush of (e, v) pairs to bucket regions.
// ---------------------------------------------------------------------------
__global__ void __launch_bounds__(P1_THREADS)
p1_bin_kernel(const int* __restrict__ ids, int n, int nbuck)
{
    __shared__ int  s_cnt[NBUCK_MAX];
    __shared__ int  s_off[NBUCK_MAX];   // inclusive scan of s_cnt
    __shared__ int  s_base[NBUCK_MAX];  // global reservation base
    __shared__ int  s_fill[NBUCK_MAX];
    __shared__ int2 s_stage[EPB];       // 32 KB

    int t = threadIdx.x;
    int start = blockIdx.x * EPB;
    int cnt_this = n - start; if (cnt_this > EPB) cnt_this = EPB;

    for (int i = t; i < nbuck; i += P1_THREADS) { s_cnt[i] = 0; s_fill[i] = 0; }
    __syncthreads();

    int myv[EPB / P1_THREADS];          // 8 per thread
    #pragma unroll
    for (int k = 0; k < EPB / P1_THREADS; k++) {
        int idx = start + k * P1_THREADS + t;
        int v = -1;
        if (idx < n) { v = __ldg(ids + idx); atomicAdd(&s_cnt[v >> VB_SHIFT], 1); }
        myv[k] = v;
    }
    __syncthreads();

    // inclusive Hillis-Steele scan of s_cnt -> s_off (nbuck <= 512 entries)
    for (int i = t; i < nbuck; i += P1_THREADS) s_off[i] = s_cnt[i];
    __syncthreads();
    for (int d = 1; d < nbuck; d <<= 1) {
        int add = 0;
        if (t < nbuck && t >= d) add = s_off[t - d];
        __syncthreads();
        if (t < nbuck) s_off[t] += add;
        __syncthreads();
    }

    // global reservation (one atomic per touched bucket)
    for (int i = t; i < nbuck; i += P1_THREADS) {
        int c = s_cnt[i];
        s_base[i] = (c > 0) ? atomicAdd(&g_bucket_cnt[i], c) : 0;
    }
    __syncthreads();

    // stage into smem grouped by bucket
    #pragma unroll
    for (int k = 0; k < EPB / P1_THREADS; k++) {
        int v = myv[k];
        if (v >= 0) {
            int b = v >> VB_SHIFT;
            int r = atomicAdd(&s_fill[b], 1);
            int p = (s_off[b] - s_cnt[b]) + r;     // exclusive offset + rank
            s_stage[p] = make_int2(start + k * P1_THREADS + t, v);
        }
    }
    __syncthreads();

    // coalesced flush (entries of one bucket are contiguous in smem and gmem)
    for (int i = t; i < cnt_this; i += P1_THREADS) {
        int2 ent = s_stage[i];
        int b = ent.y >> VB_SHIFT;
        int r = i - (s_off[b] - s_cnt[b]);
        int gpos = s_base[b] + r;
        if (gpos < CAP_B) {
            g_bucket[(size_t)b * CAP_B + gpos] = ent;
        } else {                                    // exact overflow path
            int o = atomicAdd(&g_over_n, 1);
            if (o < OVER_MAX) g_over[o] = ent;
            atomicAdd(&g_ovcnt[ent.y], 1);
        }
    }
}

// ---------------------------------------------------------------------------
// P2: per-bucket fine sort, fully in smem. One block per bucket.
// Dynamic smem layout: s_cnt[VB] | s_off[VB] | s_perm[CAP_B]  (160 KB).
// ---------------------------------------------------------------------------
__global__ void __launch_bounds__(1024)
p2_sort_kernel(int V, int nbuck)
{
    extern __shared__ int sm[];
    int* s_cnt  = sm;
    int* s_off  = sm + VB;
    int* s_perm = sm + 2 * VB;
    __shared__ int s_wsum[32];
    __shared__ int s_base_sh;

    int b = blockIdx.x;
    int t = threadIdx.x;
    int lane = t & 31, wid = t >> 5;
    int vbase = b << VB_SHIFT;
    int nv = V - vbase; if (nv > VB) nv = VB;

    int m = g_bucket_cnt[b]; if (m > CAP_B) m = CAP_B;

    // global base = sum_{j<b} min(cnt[j], CAP_B)
    {
        int partial = 0;
        for (int j = t; j < b; j += 1024) {
            int c = g_bucket_cnt[j]; if (c > CAP_B) c = CAP_B;
            partial += c;
        }
        #pragma unroll
        for (int d = 16; d > 0; d >>= 1)
            partial += __shfl_down_sync(0xffffffffu, partial, d);
        if (lane == 0) s_wsum[wid] = partial;
        __syncthreads();
        if (t < 32) {
            int x = s_wsum[t];
            #pragma unroll
            for (int d = 16; d > 0; d >>= 1)
                x += __shfl_down_sync(0xffffffffu, x, d);
            if (t == 0) s_base_sh = x;
        }
        __syncthreads();
    }
    int base = s_base_sh;

    const int2* bk = g_bucket + (size_t)b * CAP_B;

    // smem histogram over 4096 local vertices
    for (int i = t; i < VB; i += 1024) s_cnt[i] = 0;
    __syncthreads();
    for (int i = t; i < m; i += 1024) {
        int2 e = __ldg(&bk[i]);
        atomicAdd(&s_cnt[e.y - vbase], 1);
    }
    __syncthreads();

    // block scan of 4096 counters (4 per thread, shuffle-based)
    int4 c4 = *(int4*)&s_cnt[t * 4];
    int ts = c4.x + c4.y + c4.z + c4.w;
    int incl = ts;
    #pragma unroll
    for (int d = 1; d < 32; d <<= 1) {
        int u = __shfl_up_sync(0xffffffffu, incl, d);
        if (lane >= d) incl += u;
    }
    if (lane == 31) s_wsum[wid] = incl;
    __syncthreads();
    if (wid == 0) {
        int w = s_wsum[lane];
        int ws = w;
        #pragma unroll
        for (int d = 1; d < 32; d <<= 1) {
            int u = __shfl_up_sync(0xffffffffu, ws, d);
            if (lane >= d) ws += u;
        }
        s_wsum[lane] = ws - w;
    }
    __syncthreads();
    int excl = incl - ts + s_wsum[wid];
    int4 o4;
    o4.x = excl;
    o4.y = o4.x + c4.x;
    o4.z = o4.y + c4.y;
    o4.w = o4.z + c4.z;
    *(int4*)&s_off[t * 4] = o4;
    __syncthreads();

    // publish global inclusive ends for this bucket's vertices
    for (int i = t; i < nv; i += 1024)
        g_offsets[vbase + i] = base + s_off[i] + s_cnt[i];
    __syncthreads();

    // place edges into smem perm (reuse s_cnt as fill counters)
    for (int i = t; i < VB; i += 1024) s_cnt[i] = 0;
    __syncthreads();
    for (int i = t; i < m; i += 1024) {
        int2 e = __ldg(&bk[i]);
        int vl = e.y - vbase;
        int r = atomicAdd(&s_cnt[vl], 1);
        s_perm[s_off[vl] + r] = e.x;
    }
    __syncthreads();

    // coalesced flush to dense perm
    for (int i = t; i < m; i += 1024)
        g_perm[base + i] = s_perm[i];
}

// ---------------------------------------------------------------------------
// P3: gather + mean (measured-best inner structure). 8 threads per vertex;
// thread s covers feature quad s as one float4.
// ---------------------------------------------------------------------------
__global__ void gather_kernel(const float4* __restrict__ x4,
                              float4* __restrict__ out4, int V)
{
    long long t = (long long)blockIdx.x * blockDim.x + threadIdx.x;
    int v = (int)(t >> 3);
    int s = (int)(t & 7);
    if (v >= V) return;

    int beg = (v == 0) ? 0 : __ldg(&g_offsets[v - 1]);
    int end = __ldg(&g_offsets[v]);
    int deg = (end - beg) + __ldg(&g_ovcnt[v]);

    float4 acc = make_float4(0.f, 0.f, 0.f, 0.f);

    for (int base = beg; base < end; base += 8) {
        int e[8];
        #pragma unroll
        for (int u = 0; u < 8; u++) {
            int j = base + u;
            e[u] = (j < end) ? __ldg(&g_perm[j]) : -1;
        }
        #pragma unroll
        for (int u = 0; u < 8; u++) {
            if (e[u] >= 0) {
                float4 a = __ldg(x4 + (long long)e[u] * 8 + s);
                acc.x += a.x; acc.y += a.y; acc.z += a.z; acc.w += a.w;
            }
        }
    }

    float inv = 1.0f / fmaxf((float)deg, 1.0f);
    out4[(long long)v * 8 + s] =
        make_float4(acc.x * inv, acc.y * inv, acc.z * inv, acc.w * inv);
}

// ---------------------------------------------------------------------------
// P4: exact overflow fixup (normally zero entries).
// ---------------------------------------------------------------------------
__global__ void fixup_kernel(const float4* __restrict__ x4,
                             float* __restrict__ out)
{
    int cnt = g_over_n;
    if (cnt > OVER_MAX) cnt = OVER_MAX;
    int stride = gridDim.x * blockDim.x;
    for (int i = blockIdx.x * blockDim.x + threadIdx.x; i < cnt; i += stride) {
        int2 ent = g_over[i];
        int e = ent.x, v = ent.y;
        int beg = (v == 0) ? 0 : g_offsets[v - 1];
        int end = g_offsets[v];
        float inv = 1.0f / fmaxf((float)(end - beg + g_ovcnt[v]), 1.0f);
        float* dst = out + (long long)v * 32;
        #pragma unroll
        for (int s = 0; s < 8; s++) {
            float4 a = __ldg(x4 + (long long)e * 8 + s);
            asm volatile("red.global.add.v4.f32 [%0], {%1, %2, %3, %4};"
                         :: "l"(dst + s * 4),
                            "f"(a.x * inv), "f"(a.y * inv),
                            "f"(a.z * inv), "f"(a.w * inv)
                         : "memory");
        }
    }
}

extern "C" void kernel_launch(void* const* d_in, const int* in_sizes, int n_in,
                              void* d_out, int out_size)
{
    const float4* x4  = (const float4*)d_in[0];
    const int*    ids = (const int*)d_in[1];

    int n_he = in_sizes[1];                     // element count of vertex_ids
    int V    = (int)((long long)out_size / 32); // output is [V, 32]
    int nbuck = (V + VB - 1) >> VB_SHIFT;
    if (nbuck > NBUCK_MAX) nbuck = NBUCK_MAX;   // (bench shape: V=1M -> 245)

    // Zero bucket counts, overflow counts, overflow length.
    void* p = nullptr;
    cudaGetSymbolAddress(&p, g_bucket_cnt);
    cudaMemsetAsync(p, 0, (size_t)nbuck * sizeof(int));
    cudaGetSymbolAddress(&p, g_ovcnt);
    cudaMemsetAsync(p, 0, (size_t)V * sizeof(int));
    cudaGetSymbolAddress(&p, g_over_n);
    cudaMemsetAsync(p, 0, sizeof(int));

    // P1: coarse binning.
    p1_bin_kernel<<<(n_he + EPB - 1) / EPB, P1_THREADS>>>(ids, n_he, nbuck);

    // P2: per-bucket fine sort (160 KB dynamic smem).
    size_t smem = (size_t)(2 * VB + CAP_B) * sizeof(int);
    cudaFuncSetAttribute(p2_sort_kernel,
                         cudaFuncAttributeMaxDynamicSharedMemorySize, (int)smem);
    p2_sort_kernel<<<nbuck, 1024, smem>>>(V, nbuck);

    // P3: gather + mean.
    {
        long long total = (long long)V * 8;
        int threads = 256;
        int blocks = (int)((total + threads - 1) / threads);
        gather_kernel<<<blocks, threads>>>(x4, (float4*)d_out, V);
    }

    // P4: exact overflow fixup (tiny; normally exits immediately).
    fixup_kernel<<<32, 256>>>(x4, (float*)d_out);
}

// round 15
// speedup vs baseline: 1.2033x; 1.0265x over previous
#include <cuda_runtime.h>
#include <cuda_bf16.h>
#include <cstdint>

// ---------------------------------------------------------------------------
// Two-level counting sort + gather.
//   P1: coarse-bin edges into 2048-vertex buckets (smem staging, coalesced
//       global writes, ~1 global atomic per bucket per block).
//   P2: per-bucket fine sort in smem (80 KB -> 2 CTAs/SM) -> dense perm.
//   P3: gather + mean (measured-best inner loop).
//   P4: exact fixup for bucket-capacity overflow (normally empty).
// ---------------------------------------------------------------------------
#define VB_SHIFT   11
#define VB         2048                 // vertices per coarse bucket
#define NBUCK_MAX  1024                 // supports V <= 2M
#define CAP_B      16384                // binned-edge capacity per bucket
#define EPB        4096                 // edges per P1 block
#define P1_THREADS 512
#define OVER_MAX   (1 << 20)

__device__ int2 g_bucket[(size_t)NBUCK_MAX * CAP_B];  // coarse bins (e, v)
__device__ int  g_bucket_cnt[NBUCK_MAX];              // edges per bucket
__device__ int  g_offsets[2u << 20];                  // global inclusive ends
__device__ int  g_perm[8u << 20];                     // dense sorted edge ids
__device__ int  g_ovcnt[2u << 20];                    // per-vertex overflow
__device__ int  g_over_n;
__device__ int2 g_over[OVER_MAX];                     // overflow (e, v)

// ---------------------------------------------------------------------------
// P1: coarse binning. Per 4096-edge block: smem histogram over buckets,
// 2-level shuffle scan, one global atomic reservation per touched bucket,
// smem staging, coalesced flush of (e, v) pairs.
// ---------------------------------------------------------------------------
__global__ void __launch_bounds__(P1_THREADS)
p1_bin_kernel(const int* __restrict__ ids, int n, int nbuck)
{
    __shared__ int  s_cnt[NBUCK_MAX];
    __shared__ int  s_off[NBUCK_MAX];   // EXCLUSIVE offsets within block
    __shared__ int  s_base[NBUCK_MAX];  // global reservation base
    __shared__ int  s_fill[NBUCK_MAX];
    __shared__ int  s_wsum[32];
    __shared__ int2 s_stage[EPB];       // 32 KB

    int t = threadIdx.x;
    int lane = t & 31, wid = t >> 5;
    int start = blockIdx.x * EPB;
    int cnt_this = n - start; if (cnt_this > EPB) cnt_this = EPB;

    for (int i = t; i < nbuck; i += P1_THREADS) { s_cnt[i] = 0; s_fill[i] = 0; }
    __syncthreads();

    // Load 8 ids per thread (2 x int4 when fully in range) + smem histogram.
    int myv[8];
    int ebase = start + t * 8;
    if (ebase + 8 <= n) {
        int4 a = __ldg((const int4*)(ids + ebase));
        int4 b = __ldg((const int4*)(ids + ebase + 4));
        myv[0] = a.x; myv[1] = a.y; myv[2] = a.z; myv[3] = a.w;
        myv[4] = b.x; myv[5] = b.y; myv[6] = b.z; myv[7] = b.w;
    } else {
        #pragma unroll
        for (int k = 0; k < 8; k++)
            myv[k] = (ebase + k < n) ? __ldg(ids + ebase + k) : -1;
    }
    #pragma unroll
    for (int k = 0; k < 8; k++)
        if (myv[k] >= 0) atomicAdd(&s_cnt[myv[k] >> VB_SHIFT], 1);
    __syncthreads();

    // Exclusive scan of s_cnt (nbuck <= 1024), 2 entries per thread.
    {
        int i0 = t * 2;
        int c0 = (i0     < nbuck) ? s_cnt[i0]     : 0;
        int c1 = (i0 + 1 < nbuck) ? s_cnt[i0 + 1] : 0;
        int ts = c0 + c1;
        int incl = ts;
        #pragma unroll
        for (int d = 1; d < 32; d <<= 1) {
            int u = __shfl_up_sync(0xffffffffu, incl, d);
            if (lane >= d) incl += u;
        }
        if (lane == 31) s_wsum[wid] = incl;
        __syncthreads();
        if (wid == 0) {
            int w = (lane < P1_THREADS / 32) ? s_wsum[lane] : 0;
            int ws = w;
            #pragma unroll
            for (int d = 1; d < 32; d <<= 1) {
                int u = __shfl_up_sync(0xffffffffu, ws, d);
                if (lane >= d) ws += u;
            }
            s_wsum[lane] = ws - w;
        }
        __syncthreads();
        int excl = incl - ts + s_wsum[wid];
        if (i0     < nbuck) s_off[i0]     = excl;
        if (i0 + 1 < nbuck) s_off[i0 + 1] = excl + c0;
    }
    __syncthreads();

    // Global reservation (one atomic per touched bucket).
    for (int i = t; i < nbuck; i += P1_THREADS) {
        int c = s_cnt[i];
        s_base[i] = (c > 0) ? atomicAdd(&g_bucket_cnt[i], c) : 0;
    }
    __syncthreads();

    // Stage into smem grouped by bucket.
    #pragma unroll
    for (int k = 0; k < 8; k++) {
        int v = myv[k];
        if (v >= 0) {
            int b = v >> VB_SHIFT;
            int r = atomicAdd(&s_fill[b], 1);
            s_stage[s_off[b] + r] = make_int2(ebase + k, v);
        }
    }
    __syncthreads();

    // Coalesced flush.
    for (int i = t; i < cnt_this; i += P1_THREADS) {
        int2 ent = s_stage[i];
        int b = ent.y >> VB_SHIFT;
        int gpos = s_base[b] + (i - s_off[b]);
        if (gpos < CAP_B) {
            g_bucket[(size_t)b * CAP_B + gpos] = ent;
        } else {                                    // exact overflow path
            int o = atomicAdd(&g_over_n, 1);
            if (o < OVER_MAX) g_over[o] = ent;
            atomicAdd(&g_ovcnt[ent.y], 1);
        }
    }
}

// ---------------------------------------------------------------------------
// P2: per-bucket fine sort, fully in smem. One block per bucket.
// Dynamic smem: s_cnt[VB] | s_off[VB] | s_perm[CAP_B] = 80 KB -> 2 CTAs/SM.
// ---------------------------------------------------------------------------
__global__ void __launch_bounds__(1024, 2)
p2_sort_kernel(int V, int nbuck)
{
    extern __shared__ int sm[];
    int* s_cnt  = sm;
    int* s_off  = sm + VB;
    int* s_perm = sm + 2 * VB;
    __shared__ int s_wsum[32];
    __shared__ int s_base_sh;

    int b = blockIdx.x;
    int t = threadIdx.x;
    int lane = t & 31, wid = t >> 5;
    int vbase = b << VB_SHIFT;
    int nv = V - vbase; if (nv > VB) nv = VB;

    int m = g_bucket_cnt[b]; if (m > CAP_B) m = CAP_B;

    // global base = sum_{j<b} min(cnt[j], CAP_B)
    {
        int partial = 0;
        for (int j = t; j < b; j += 1024) {
            int c = g_bucket_cnt[j]; if (c > CAP_B) c = CAP_B;
            partial += c;
        }
        #pragma unroll
        for (int d = 16; d > 0; d >>= 1)
            partial += __shfl_down_sync(0xffffffffu, partial, d);
        if (lane == 0) s_wsum[wid] = partial;
        __syncthreads();
        if (t < 32) {
            int x = s_wsum[t];
            #pragma unroll
            for (int d = 16; d > 0; d >>= 1)
                x += __shfl_down_sync(0xffffffffu, x, d);
            if (t == 0) s_base_sh = x;
        }
        __syncthreads();
    }
    int base = s_base_sh;

    const int2* bk = g_bucket + (size_t)b * CAP_B;

    // smem histogram over 2048 local vertices
    for (int i = t; i < VB; i += 1024) s_cnt[i] = 0;
    __syncthreads();
    for (int i = t; i < m; i += 1024) {
        int2 e = __ldg(&bk[i]);
        atomicAdd(&s_cnt[e.y - vbase], 1);
    }
    __syncthreads();

    // block scan of 2048 counters (2 per thread, shuffle-based)
    {
        int2 c2 = *(int2*)&s_cnt[t * 2];
        int ts = c2.x + c2.y;
        int incl = ts;
        #pragma unroll
        for (int d = 1; d < 32; d <<= 1) {
            int u = __shfl_up_sync(0xffffffffu, incl, d);
            if (lane >= d) incl += u;
        }
        if (lane == 31) s_wsum[wid] = incl;
        __syncthreads();
        if (wid == 0) {
            int w = s_wsum[lane];
            int ws = w;
            #pragma unroll
            for (int d = 1; d < 32; d <<= 1) {
                int u = __shfl_up_sync(0xffffffffu, ws, d);
                if (lane >= d) ws += u;
            }
            s_wsum[lane] = ws - w;
        }
        __syncthreads();
        int excl = incl - ts + s_wsum[wid];
        int2 o2;
        o2.x = excl;
        o2.y = excl + c2.x;
        *(int2*)&s_off[t * 2] = o2;
    }
    __syncthreads();

    // publish global inclusive ends for this bucket's vertices
    for (int i = t; i < nv; i += 1024)
        g_offsets[vbase + i] = base + s_off[i] + s_cnt[i];
    __syncthreads();

    // place edges into smem perm (reuse s_cnt as fill counters)
    for (int i = t; i < VB; i += 1024) s_cnt[i] = 0;
    __syncthreads();
    for (int i = t; i < m; i += 1024) {
        int2 e = __ldg(&bk[i]);
        int vl = e.y - vbase;
        int r = atomicAdd(&s_cnt[vl], 1);
        s_perm[s_off[vl] + r] = e.x;
    }
    __syncthreads();

    // coalesced flush to dense perm
    for (int i = t; i < m; i += 1024)
        g_perm[base + i] = s_perm[i];
}

// ---------------------------------------------------------------------------
// P3: gather + mean (measured-best inner structure). 8 threads per vertex;
// thread s covers feature quad s as one float4.
// ---------------------------------------------------------------------------
__global__ void gather_kernel(const float4* __restrict__ x4,
                              float4* __restrict__ out4, int V)
{
    long long t = (long long)blockIdx.x * blockDim.x + threadIdx.x;
    int v = (int)(t >> 3);
    int s = (int)(t & 7);
    if (v >= V) return;

    int beg = (v == 0) ? 0 : __ldg(&g_offsets[v - 1]);
    int end = __ldg(&g_offsets[v]);
    int deg = (end - beg) + __ldg(&g_ovcnt[v]);

    float4 acc = make_float4(0.f, 0.f, 0.f, 0.f);

    for (int base = beg; base < end; base += 8) {
        int e[8];
        #pragma unroll
        for (int u = 0; u < 8; u++) {
            int j = base + u;
            e[u] = (j < end) ? __ldg(&g_perm[j]) : -1;
        }
        #pragma unroll
        for (int u = 0; u < 8; u++) {
            if (e[u] >= 0) {
                float4 a = __ldg(x4 + (long long)e[u] * 8 + s);
                acc.x += a.x; acc.y += a.y; acc.z += a.z; acc.w += a.w;
            }
        }
    }

    float inv = 1.0f / fmaxf((float)deg, 1.0f);
    out4[(long long)v * 8 + s] =
        make_float4(acc.x * inv, acc.y * inv, acc.z * inv, acc.w * inv);
}

// ---------------------------------------------------------------------------
// P4: exact overflow fixup (normally zero entries).
// ---------------------------------------------------------------------------
__global__ void fixup_kernel(const float4* __restrict__ x4,
                             float* __restrict__ out)
{
    int cnt = g_over_n;
    if (cnt > OVER_MAX) cnt = OVER_MAX;
    int stride = gridDim.x * blockDim.x;
    for (int i = blockIdx.x * blockDim.x + threadIdx.x; i < cnt; i += stride) {
        int2 ent = g_over[i];
        int e = ent.x, v = ent.y;
        int beg = (v == 0) ? 0 : g_offsets[v - 1];
        int end = g_offsets[v];
        float inv = 1.0f / fmaxf((float)(end - beg + g_ovcnt[v]), 1.0f);
        float* dst = out + (long long)v * 32;
        #pragma unroll
        for (int s = 0; s < 8; s++) {
            float4 a = __ldg(x4 + (long long)e * 8 + s);
            asm volatile("red.global.add.v4.f32 [%0], {%1, %2, %3, %4};"
                         :: "l"(dst + s * 4),
                            "f"(a.x * inv), "f"(a.y * inv),
                            "f"(a.z * inv), "f"(a.w * inv)
                         : "memory");
        }
    }
}

extern "C" void kernel_launch(void* const* d_in, const int* in_sizes, int n_in,
                              void* d_out, int out_size)
{
    const float4* x4  = (const float4*)d_in[0];
    const int*    ids = (const int*)d_in[1];

    int n_he = in_sizes[1];                     // element count of vertex_ids
    int V    = (int)((long long)out_size / 32); // output is [V, 32]
    int nbuck = (V + VB - 1) >> VB_SHIFT;
    if (nbuck > NBUCK_MAX) nbuck = NBUCK_MAX;   // (bench shape: V=1M -> 489)

    // Zero bucket counts, overflow counts, overflow length.
    void* p = nullptr;
    cudaGetSymbolAddress(&p, g_bucket_cnt);
    cudaMemsetAsync(p, 0, (size_t)nbuck * sizeof(int));
    cudaGetSymbolAddress(&p, g_ovcnt);
    cudaMemsetAsync(p, 0, (size_t)V * sizeof(int));
    cudaGetSymbolAddress(&p, g_over_n);
    cudaMemsetAsync(p, 0, sizeof(int));

    // P1: coarse binning.
    p1_bin_kernel<<<(n_he + EPB - 1) / EPB, P1_THREADS>>>(ids, n_he, nbuck);

    // P2: per-bucket fine sort (80 KB dynamic smem -> 2 CTAs/SM).
    size_t smem = (size_t)(2 * VB + CAP_B) * sizeof(int);
    cudaFuncSetAttribute(p2_sort_kernel,
                         cudaFuncAttributeMaxDynamicSharedMemorySize, (int)smem);
    p2_sort_kernel<<<nbuck, 1024, smem>>>(V, nbuck);

    // P3: gather + mean.
    {
        long long total = (long long)V * 8;
        int threads = 256;
        int blocks = (int)((total + threads - 1) / threads);
        gather_kernel<<<blocks, threads>>>(x4, (float4*)d_out, V);
    }

    // P4: exact overflow fixup (tiny; normally exits immediately).
    fixup_kernel<<<32, 256>>>(x4, (float*)d_out);
}